// round 1
// baseline (speedup 1.0000x reference)
#include <cuda_runtime.h>
#include <cuda_bf16.h>

// Scalar accumulator + completion counter (self-resetting for graph replay).
__device__ double g_acc = 0.0;
__device__ unsigned int g_done = 0;

__device__ __forceinline__ void row_compute(float l0, float l1, float l2, int t,
                                            float& ce, float& ssq, int& k1) {
    // log-softmax
    float m   = fmaxf(l0, fmaxf(l1, l2));
    float e0  = __expf(l0 - m);
    float e1  = __expf(l1 - m);
    float e2  = __expf(l2 - m);
    float s   = e0 + e1 + e2;
    float lse = m + __logf(s);
    // cross-entropy: -(l[t] - lse)
    float lt = (t == 0) ? l0 : ((t == 1) ? l1 : l2);
    ce += lse - lt;
    // r2 pieces: alt_p = 1 - p0 ; af2 == 0.5 always (targets in {0,1,2})
    float p0 = __fdividef(e0, s);
    float d  = 0.5f - p0;           // (1 - p0) - 0.5
    ssq += d * d;
    k1  += (t == 1) ? 1 : 0;
    // KL term p*(log p - lp) is identically 0 in exact math; reference's value
    // is float rounding noise (~1e-4 total vs ~9e6 loss) -> omitted.
}

__global__ void imputation_loss_kernel(const float* __restrict__ logits,
                                       const int*   __restrict__ targets,
                                       float* __restrict__ out,
                                       int n, int numGroups) {
    int g = blockIdx.x * blockDim.x + threadIdx.x;
    float local = 0.0f;
    if (g < numGroups) {
        int base = g * 4;
        float ce = 0.0f, ssq = 0.0f;
        int k1 = 0;
        if (base + 4 <= n) {
            // group of 4 rows = 12 floats = 3 aligned float4; 4 targets = 1 int4
            const float4* lp = reinterpret_cast<const float4*>(logits) + (size_t)g * 3;
            float4 a = lp[0];
            float4 b = lp[1];
            float4 c = lp[2];
            int4 t4 = reinterpret_cast<const int4*>(targets)[g];
            row_compute(a.x, a.y, a.z, t4.x, ce, ssq, k1);
            row_compute(a.w, b.x, b.y, t4.y, ce, ssq, k1);
            row_compute(b.z, b.w, c.x, t4.z, ce, ssq, k1);
            row_compute(c.y, c.z, c.w, t4.w, ce, ssq, k1);
            // r2 contribution of a full group: -(mse/denom)*cnt per t==1 row
            //   = -(ssq/4)/0.25*4 * k1 = -4*ssq*k1
            local = ce - 4.0f * ssq * (float)k1;
        } else {
            // generic tail (unused for N % 4 == 0, kept for safety)
            int cnt = 0;
            for (int i = base; i < n; ++i) {
                row_compute(logits[3 * i], logits[3 * i + 1], logits[3 * i + 2],
                            targets[i], ce, ssq, k1);
                cnt++;
            }
            if (cnt > 0) {
                float mse = ssq / (float)cnt;           // cnt >= 1
                local = ce - 4.0f * mse * (float)cnt * (float)k1;
            }
        }
    }

    // block reduction in double
    double v = (double)local;
    #pragma unroll
    for (int o = 16; o; o >>= 1) v += __shfl_down_sync(0xffffffffu, v, o);
    __shared__ double ws[32];
    int lane = threadIdx.x & 31;
    int wid  = threadIdx.x >> 5;
    if (lane == 0) ws[wid] = v;
    __syncthreads();
    int nw = (blockDim.x + 31) >> 5;
    if (wid == 0) {
        v = (lane < nw) ? ws[lane] : 0.0;
        #pragma unroll
        for (int o = 16; o; o >>= 1) v += __shfl_down_sync(0xffffffffu, v, o);
        if (lane == 0) {
            atomicAdd(&g_acc, v);
            __threadfence();
            unsigned int done = atomicAdd(&g_done, 1u);
            if (done == gridDim.x - 1) {
                // last block: publish result and reset state for next replay
                double total = atomicAdd(&g_acc, 0.0);
                out[0] = (float)total;
                g_acc  = 0.0;
                g_done = 0;
            }
        }
    }
}

extern "C" void kernel_launch(void* const* d_in, const int* in_sizes, int n_in,
                              void* d_out, int out_size) {
    const float* logits  = (const float*)d_in[0];
    const int*   targets = (const int*)d_in[1];
    float* out = (float*)d_out;
    int n = in_sizes[1];                 // number of rows (targets count)
    int numGroups = (n + 3) / 4;
    int threads = 256;
    int blocks = (numGroups + threads - 1) / threads;
    imputation_loss_kernel<<<blocks, threads>>>(logits, targets, out, n, numGroups);
}

// round 2
// speedup vs baseline: 1.1517x; 1.1517x over previous
#include <cuda_runtime.h>
#include <cuda_bf16.h>

// Scalar accumulator + completion counter (self-resetting for graph replay).
__device__ double g_acc = 0.0;
__device__ unsigned int g_done = 0;

__device__ __forceinline__ void row_compute(float l0, float l1, float l2, int t,
                                            float& ce, float& ssq, int& k1) {
    float m   = fmaxf(l0, fmaxf(l1, l2));
    float e0  = __expf(l0 - m);
    float e1  = __expf(l1 - m);
    float e2  = __expf(l2 - m);
    float s   = e0 + e1 + e2;
    float lse = m + __logf(s);
    float lt  = (t == 0) ? l0 : ((t == 1) ? l1 : l2);
    ce += lse - lt;
    float p0 = __fdividef(e0, s);
    float d  = 0.5f - p0;            // (1 - p0) - 0.5 ; af2 == 0.5 since t in {0,1,2}
    ssq += d * d;
    k1  += (t == 1) ? 1 : 0;
    // KL term p*(log p - lp) == 0 exactly; reference value is float noise -> omitted.
}

// One thread = 2 groups = 8 rows = 24 floats (6x float4) + 8 targets (2x int4).
// All 8 loads issued up front (MLP_p1=8) to keep DRAM pipeline full.
__global__ void imputation_loss_kernel(const float* __restrict__ logits,
                                       const int*   __restrict__ targets,
                                       float* __restrict__ out,
                                       int n, int numPairs) {
    int p = blockIdx.x * blockDim.x + threadIdx.x;
    float local = 0.0f;

    if (p < numPairs) {
        const float4* lp = reinterpret_cast<const float4*>(logits) + (size_t)p * 6;
        const int4*   tp = reinterpret_cast<const int4*>(targets) + (size_t)p * 2;
        // batch all loads (streaming: single-use data, no L2 allocate)
        float4 a = __ldcs(lp + 0);
        float4 b = __ldcs(lp + 1);
        float4 c = __ldcs(lp + 2);
        float4 d = __ldcs(lp + 3);
        float4 e = __ldcs(lp + 4);
        float4 f = __ldcs(lp + 5);
        int4 t0 = __ldcs(tp + 0);
        int4 t1 = __ldcs(tp + 1);

        // group A (rows 8p..8p+3)
        float ceA = 0.0f, ssqA = 0.0f; int k1A = 0;
        row_compute(a.x, a.y, a.z, t0.x, ceA, ssqA, k1A);
        row_compute(a.w, b.x, b.y, t0.y, ceA, ssqA, k1A);
        row_compute(b.z, b.w, c.x, t0.z, ceA, ssqA, k1A);
        row_compute(c.y, c.z, c.w, t0.w, ceA, ssqA, k1A);
        // group B (rows 8p+4..8p+7)
        float ceB = 0.0f, ssqB = 0.0f; int k1B = 0;
        row_compute(d.x, d.y, d.z, t1.x, ceB, ssqB, k1B);
        row_compute(d.w, e.x, e.y, t1.y, ceB, ssqB, k1B);
        row_compute(e.z, e.w, f.x, t1.z, ceB, ssqB, k1B);
        row_compute(f.y, f.z, f.w, t1.w, ceB, ssqB, k1B);

        // per-group R2: -(ssq/cnt)/0.25 * cnt * k1 = -4*ssq*k1 (cnt cancels)
        local = (ceA - 4.0f * ssqA * (float)k1A)
              + (ceB - 4.0f * ssqB * (float)k1B);
    }

    // Tail rows beyond full pairs (group boundaries align at numPairs*8).
    if (p == 0) {
        for (int base = numPairs * 8; base < n; base += 4) {
            float ce = 0.0f, ssq = 0.0f; int k1 = 0;
            int end = min(base + 4, n);
            for (int i = base; i < end; ++i) {
                row_compute(logits[3 * i], logits[3 * i + 1], logits[3 * i + 2],
                            targets[i], ce, ssq, k1);
            }
            local += ce - 4.0f * ssq * (float)k1;   // cnt cancels here too
        }
    }

    // block reduction in double
    double v = (double)local;
    #pragma unroll
    for (int o = 16; o; o >>= 1) v += __shfl_down_sync(0xffffffffu, v, o);
    __shared__ double ws[32];
    int lane = threadIdx.x & 31;
    int wid  = threadIdx.x >> 5;
    if (lane == 0) ws[wid] = v;
    __syncthreads();
    int nw = (blockDim.x + 31) >> 5;
    if (wid == 0) {
        v = (lane < nw) ? ws[lane] : 0.0;
        #pragma unroll
        for (int o = 16; o; o >>= 1) v += __shfl_down_sync(0xffffffffu, v, o);
        if (lane == 0) {
            atomicAdd(&g_acc, v);
            __threadfence();
            unsigned int done = atomicAdd(&g_done, 1u);
            if (done == gridDim.x - 1) {
                double total = atomicAdd(&g_acc, 0.0);
                out[0] = (float)total;
                g_acc  = 0.0;
                g_done = 0;
            }
        }
    }
}

extern "C" void kernel_launch(void* const* d_in, const int* in_sizes, int n_in,
                              void* d_out, int out_size) {
    const float* logits  = (const float*)d_in[0];
    const int*   targets = (const int*)d_in[1];
    float* out = (float*)d_out;
    int n = in_sizes[1];                 // number of rows
    int numPairs = n / 8;                // threads handling 2 full groups each
    int threads = 256;
    int blocks = (numPairs + threads - 1) / threads;
    if (blocks < 1) blocks = 1;
    imputation_loss_kernel<<<blocks, threads>>>(logits, targets, out, n, numPairs);
}